// round 1
// baseline (speedup 1.0000x reference)
#include <cuda_runtime.h>
#include <cstdint>
#include <cstddef>

#define N_NODES   100000
#define N_EDGES   1600000
#define IN_F      64
#define OUT_F     64
#define KK        4
#define HCOLS     (KK * OUT_F)   // 256

// Scratch for node projections h = feat @ W^T, layout [N, K*OUT] row-major.
__device__ float g_h[(size_t)N_NODES * HCOLS];

// ---------------------------------------------------------------------------
// Kernel 1: h = feat @ W_fc^T  and  out = feat + bias   (residual init)
// Block: 256 threads, 32 node-rows per block. Grid = 100000/32 = 3125 exact.
// smem: feat tile [32][64], W chunk transposed [64][68] (pad keeps 16B align).
// ---------------------------------------------------------------------------
__global__ __launch_bounds__(256) void proj_kernel(
    const float* __restrict__ feat,
    const float* __restrict__ W,      // [256, 64]
    const float* __restrict__ bias,   // [64]
    float* __restrict__ out)
{
    __shared__ float sfeat[32][64];
    __shared__ float sW[64][68];      // sW[i][j_local]: transposed W chunk

    const int tid  = threadIdx.x;
    const int row0 = blockIdx.x * 32;

    // Load feat tile (32x64 = 512 float4) and write out = feat + bias.
    #pragma unroll
    for (int t = 0; t < 2; t++) {
        int idx = tid + t * 256;          // 0..511
        int r   = idx >> 4;               // 0..31
        int c4  = idx & 15;               // 0..15
        float4 v = *reinterpret_cast<const float4*>(
            feat + (size_t)(row0 + r) * IN_F + c4 * 4);
        *reinterpret_cast<float4*>(&sfeat[r][c4 * 4]) = v;
        float4 b = *reinterpret_cast<const float4*>(bias + c4 * 4);
        v.x += b.x; v.y += b.y; v.z += b.z; v.w += b.w;
        *reinterpret_cast<float4*>(
            out + (size_t)(row0 + r) * OUT_F + c4 * 4) = v;
    }

    const int cg = tid & 15;     // column group within 64-col chunk: cols cg*4..+3
    const int r0 = (tid >> 4) * 2;  // rows r0, r0+1

    for (int ch = 0; ch < 4; ch++) {
        __syncthreads();   // protects sW reuse (and sfeat on first iter)
        // Stage W chunk (rows ch*64..+63 of W[256][64]) transposed into sW.
        #pragma unroll
        for (int t = 0; t < 4; t++) {
            int idx = tid + t * 256;       // 0..1023
            int j   = idx >> 4;            // 0..63 (output col within chunk)
            int i4  = idx & 15;            // K-group
            float4 w = *reinterpret_cast<const float4*>(
                W + (size_t)(ch * 64 + j) * IN_F + i4 * 4);
            sW[i4 * 4 + 0][j] = w.x;
            sW[i4 * 4 + 1][j] = w.y;
            sW[i4 * 4 + 2][j] = w.z;
            sW[i4 * 4 + 3][j] = w.w;
        }
        __syncthreads();

        float4 acc0 = make_float4(0.f, 0.f, 0.f, 0.f);
        float4 acc1 = make_float4(0.f, 0.f, 0.f, 0.f);
        #pragma unroll
        for (int i4 = 0; i4 < 16; i4++) {
            float4 a0 = *reinterpret_cast<const float4*>(&sfeat[r0 + 0][i4 * 4]);
            float4 a1 = *reinterpret_cast<const float4*>(&sfeat[r0 + 1][i4 * 4]);
            float4 b0 = *reinterpret_cast<const float4*>(&sW[i4 * 4 + 0][cg * 4]);
            float4 b1 = *reinterpret_cast<const float4*>(&sW[i4 * 4 + 1][cg * 4]);
            float4 b2 = *reinterpret_cast<const float4*>(&sW[i4 * 4 + 2][cg * 4]);
            float4 b3 = *reinterpret_cast<const float4*>(&sW[i4 * 4 + 3][cg * 4]);
            acc0.x += a0.x * b0.x; acc0.y += a0.x * b0.y; acc0.z += a0.x * b0.z; acc0.w += a0.x * b0.w;
            acc0.x += a0.y * b1.x; acc0.y += a0.y * b1.y; acc0.z += a0.y * b1.z; acc0.w += a0.y * b1.w;
            acc0.x += a0.z * b2.x; acc0.y += a0.z * b2.y; acc0.z += a0.z * b2.z; acc0.w += a0.z * b2.w;
            acc0.x += a0.w * b3.x; acc0.y += a0.w * b3.y; acc0.z += a0.w * b3.z; acc0.w += a0.w * b3.w;
            acc1.x += a1.x * b0.x; acc1.y += a1.x * b0.y; acc1.z += a1.x * b0.z; acc1.w += a1.x * b0.w;
            acc1.x += a1.y * b1.x; acc1.y += a1.y * b1.y; acc1.z += a1.y * b1.z; acc1.w += a1.y * b1.w;
            acc1.x += a1.z * b2.x; acc1.y += a1.z * b2.y; acc1.z += a1.z * b2.z; acc1.w += a1.z * b2.w;
            acc1.x += a1.w * b3.x; acc1.y += a1.w * b3.y; acc1.z += a1.w * b3.z; acc1.w += a1.w * b3.w;
        }
        float* hp0 = g_h + (size_t)(row0 + r0 + 0) * HCOLS + ch * 64 + cg * 4;
        float* hp1 = g_h + (size_t)(row0 + r0 + 1) * HCOLS + ch * 64 + cg * 4;
        *reinterpret_cast<float4*>(hp0) = acc0;
        *reinterpret_cast<float4*>(hp1) = acc1;
    }
}

// ---------------------------------------------------------------------------
// Kernel 2: per-edge gather + weighted combine + vector-atomic scatter.
// Block: 256 threads = 16 edges (16 threads per edge, 4 floats per thread).
// Phase 1: 64 threads compute the 16x4 Gaussian weights (1 exp per lane,
//          full MUFU lane utilization) into smem.
// Phase 2: each 16-thread group gathers 4x float4 of h[src], combines with g,
//          one red.global.add.v4.f32 per thread into out[dst].
// Grid = 1.6M/16 = 100000 exact.
// ---------------------------------------------------------------------------
__global__ __launch_bounds__(256) void edge_kernel(
    const float* __restrict__ pseudo,     // [E,3]
    const int*   __restrict__ src,
    const int*   __restrict__ dst,
    const float* __restrict__ mu,         // [4,3]
    const float* __restrict__ inv_sigma,  // [4,3]
    float* __restrict__ out)
{
    __shared__ float4 sg[16];   // Gaussian weights per local edge
    __shared__ int ssrc[16];
    __shared__ int sdst[16];

    const int tid = threadIdx.x;
    const int e0  = blockIdx.x * 16;

    if (tid < 64) {
        int el = tid >> 2;     // local edge 0..15
        int k  = tid & 3;      // kernel index
        int e  = e0 + el;
        float p0 = __ldg(pseudo + 3 * (size_t)e + 0);
        float p1 = __ldg(pseudo + 3 * (size_t)e + 1);
        float p2 = __ldg(pseudo + 3 * (size_t)e + 2);
        float m0 = __ldg(mu + 3 * k + 0);
        float m1 = __ldg(mu + 3 * k + 1);
        float m2 = __ldg(mu + 3 * k + 2);
        float s0 = __ldg(inv_sigma + 3 * k + 0);
        float s1 = __ldg(inv_sigma + 3 * k + 1);
        float s2 = __ldg(inv_sigma + 3 * k + 2);
        float dx = p0 - m0, dy = p1 - m1, dz = p2 - m2;
        float w = dx * dx * s0 * s0 + dy * dy * s1 * s1 + dz * dz * s2 * s2;
        reinterpret_cast<float*>(&sg[el])[k] = __expf(-0.5f * w);
        if (k == 0) {
            ssrc[el] = src[e];
            sdst[el] = dst[e];
        }
    }
    __syncthreads();

    const int el = tid >> 4;   // local edge 0..15
    const int c  = tid & 15;   // column group: cols c*4..c*4+3
    const int s  = ssrc[el];
    const int d  = sdst[el];
    const float4 g = sg[el];

    const float4* hp = reinterpret_cast<const float4*>(
        g_h + (size_t)s * HCOLS) + c;
    float4 h0 = __ldg(hp + 0);    // k = 0
    float4 h1 = __ldg(hp + 16);   // k = 1
    float4 h2 = __ldg(hp + 32);   // k = 2
    float4 h3 = __ldg(hp + 48);   // k = 3

    float4 acc;
    acc.x = g.x * h0.x + g.y * h1.x + g.z * h2.x + g.w * h3.x;
    acc.y = g.x * h0.y + g.y * h1.y + g.z * h2.y + g.w * h3.y;
    acc.z = g.x * h0.z + g.y * h1.z + g.z * h2.z + g.w * h3.z;
    acc.w = g.x * h0.w + g.y * h1.w + g.z * h2.w + g.w * h3.w;

    float* op = out + (size_t)d * OUT_F + (c << 2);
    asm volatile(
        "red.global.add.v4.f32 [%0], {%1, %2, %3, %4};"
        :: "l"(op), "f"(acc.x), "f"(acc.y), "f"(acc.z), "f"(acc.w)
        : "memory");
}

// ---------------------------------------------------------------------------
extern "C" void kernel_launch(void* const* d_in, const int* in_sizes, int n_in,
                              void* d_out, int out_size)
{
    const float* feat      = (const float*)d_in[0];
    const float* pseudo    = (const float*)d_in[1];
    const int*   src       = (const int*)d_in[2];
    const int*   dst       = (const int*)d_in[3];
    const float* W_fc      = (const float*)d_in[4];
    const float* mu        = (const float*)d_in[5];
    const float* inv_sigma = (const float*)d_in[6];
    const float* bias      = (const float*)d_in[7];
    float* out = (float*)d_out;

    proj_kernel<<<N_NODES / 32, 256>>>(feat, W_fc, bias, out);
    edge_kernel<<<N_EDGES / 16, 256>>>(pseudo, src, dst, mu, inv_sigma, out);
}

// round 2
// speedup vs baseline: 1.9449x; 1.9449x over previous
#include <cuda_runtime.h>
#include <cuda_fp16.h>
#include <cstdint>
#include <cstddef>

#define N_NODES   100000
#define N_EDGES   1600000
#define IN_F      64
#define OUT_F     64
#define KK        4
#define HCOLS     (KK * OUT_F)   // 256

// Node projections h = feat @ W^T, fp16, layout [N, 256] row-major. 51.2 MB.
__device__ __half g_h16[(size_t)N_NODES * HCOLS];

// ---------------------------------------------------------------------------
// Kernel 1: h = feat @ W_fc^T (fp16 HMMA, fp32 accum) and out = feat + bias.
// Block: 256 threads (8 warps), 64 node-rows per block. BN = 256 (all cols).
// Warp tile: 16 rows x 128 cols -> 16 n-tiles of m16n8k16, 4 k-steps.
// smem: sA fp16 [64][72] (pad 72 -> conflict-free frag loads),
//       sW fp16 [256][72].
// ---------------------------------------------------------------------------
__global__ __launch_bounds__(256) void proj_kernel(
    const float* __restrict__ feat,
    const float* __restrict__ W,      // [256, 64]
    const float* __restrict__ bias,   // [64]
    float* __restrict__ out)
{
    __shared__ __half sA[64][72];
    __shared__ __half sW[256][72];

    const int tid  = threadIdx.x;
    const int row0 = blockIdx.x * 64;

    // ---- Stage feat tile (fp32 -> fp16) and write out = feat + bias ----
    {
        const int r  = tid >> 2;          // 0..63
        const int cb = (tid & 3) * 16;    // 0,16,32,48
        const int gr  = row0 + r;
        const int grc = gr < N_NODES ? gr : (N_NODES - 1);
        const float4* fp = reinterpret_cast<const float4*>(
            feat + (size_t)grc * IN_F + cb);
        float4 v0 = __ldg(fp + 0);
        float4 v1 = __ldg(fp + 1);
        float4 v2 = __ldg(fp + 2);
        float4 v3 = __ldg(fp + 3);
        __half* ap = &sA[r][cb];
        *reinterpret_cast<__half2*>(ap + 0)  = __float22half2_rn(make_float2(v0.x, v0.y));
        *reinterpret_cast<__half2*>(ap + 2)  = __float22half2_rn(make_float2(v0.z, v0.w));
        *reinterpret_cast<__half2*>(ap + 4)  = __float22half2_rn(make_float2(v1.x, v1.y));
        *reinterpret_cast<__half2*>(ap + 6)  = __float22half2_rn(make_float2(v1.z, v1.w));
        *reinterpret_cast<__half2*>(ap + 8)  = __float22half2_rn(make_float2(v2.x, v2.y));
        *reinterpret_cast<__half2*>(ap + 10) = __float22half2_rn(make_float2(v2.z, v2.w));
        *reinterpret_cast<__half2*>(ap + 12) = __float22half2_rn(make_float2(v3.x, v3.y));
        *reinterpret_cast<__half2*>(ap + 14) = __float22half2_rn(make_float2(v3.z, v3.w));
        if (gr < N_NODES) {
            const float4* bp = reinterpret_cast<const float4*>(bias + cb);
            float4 b0 = __ldg(bp + 0), b1 = __ldg(bp + 1);
            float4 b2 = __ldg(bp + 2), b3 = __ldg(bp + 3);
            float4* op = reinterpret_cast<float4*>(out + (size_t)gr * OUT_F + cb);
            v0.x += b0.x; v0.y += b0.y; v0.z += b0.z; v0.w += b0.w;
            v1.x += b1.x; v1.y += b1.y; v1.z += b1.z; v1.w += b1.w;
            v2.x += b2.x; v2.y += b2.y; v2.z += b2.z; v2.w += b2.w;
            v3.x += b3.x; v3.y += b3.y; v3.z += b3.z; v3.w += b3.w;
            op[0] = v0; op[1] = v1; op[2] = v2; op[3] = v3;
        }
    }

    // ---- Stage W (fp32 -> fp16): 256x64 ----
    #pragma unroll
    for (int p = 0; p < 4; p++) {
        const int r  = p * 64 + (tid >> 2);
        const int cb = (tid & 3) * 16;
        const float4* wp = reinterpret_cast<const float4*>(
            W + (size_t)r * IN_F + cb);
        float4 v0 = __ldg(wp + 0);
        float4 v1 = __ldg(wp + 1);
        float4 v2 = __ldg(wp + 2);
        float4 v3 = __ldg(wp + 3);
        __half* ap = &sW[r][cb];
        *reinterpret_cast<__half2*>(ap + 0)  = __float22half2_rn(make_float2(v0.x, v0.y));
        *reinterpret_cast<__half2*>(ap + 2)  = __float22half2_rn(make_float2(v0.z, v0.w));
        *reinterpret_cast<__half2*>(ap + 4)  = __float22half2_rn(make_float2(v1.x, v1.y));
        *reinterpret_cast<__half2*>(ap + 6)  = __float22half2_rn(make_float2(v1.z, v1.w));
        *reinterpret_cast<__half2*>(ap + 8)  = __float22half2_rn(make_float2(v2.x, v2.y));
        *reinterpret_cast<__half2*>(ap + 10) = __float22half2_rn(make_float2(v2.z, v2.w));
        *reinterpret_cast<__half2*>(ap + 12) = __float22half2_rn(make_float2(v3.x, v3.y));
        *reinterpret_cast<__half2*>(ap + 14) = __float22half2_rn(make_float2(v3.z, v3.w));
    }
    __syncthreads();

    const int lane = tid & 31;
    const int wid  = tid >> 5;
    const int m_base = (wid & 3) * 16;     // warp row group
    const int n_base = (wid >> 2) * 128;   // warp col group
    const int g   = lane >> 2;             // group id 0..7
    const int tig = lane & 3;              // thread in group

    float acc[16][4];
    #pragma unroll
    for (int nt = 0; nt < 16; nt++) {
        acc[nt][0] = 0.f; acc[nt][1] = 0.f; acc[nt][2] = 0.f; acc[nt][3] = 0.f;
    }

    #pragma unroll
    for (int kt = 0; kt < 4; kt++) {
        const int k0 = kt * 16;
        uint32_t a0 = *reinterpret_cast<const uint32_t*>(&sA[m_base + g    ][k0 + tig * 2    ]);
        uint32_t a1 = *reinterpret_cast<const uint32_t*>(&sA[m_base + g + 8][k0 + tig * 2    ]);
        uint32_t a2 = *reinterpret_cast<const uint32_t*>(&sA[m_base + g    ][k0 + tig * 2 + 8]);
        uint32_t a3 = *reinterpret_cast<const uint32_t*>(&sA[m_base + g + 8][k0 + tig * 2 + 8]);
        #pragma unroll
        for (int nt = 0; nt < 16; nt++) {
            const int n = n_base + nt * 8 + g;
            uint32_t b0 = *reinterpret_cast<const uint32_t*>(&sW[n][k0 + tig * 2    ]);
            uint32_t b1 = *reinterpret_cast<const uint32_t*>(&sW[n][k0 + tig * 2 + 8]);
            asm volatile(
                "mma.sync.aligned.m16n8k16.row.col.f32.f16.f16.f32 "
                "{%0,%1,%2,%3}, {%4,%5,%6,%7}, {%8,%9}, {%0,%1,%2,%3};"
                : "+f"(acc[nt][0]), "+f"(acc[nt][1]),
                  "+f"(acc[nt][2]), "+f"(acc[nt][3])
                : "r"(a0), "r"(a1), "r"(a2), "r"(a3), "r"(b0), "r"(b1));
        }
    }

    // ---- Store h fp16 ----
    const int r0 = row0 + m_base + g;
    #pragma unroll
    for (int nt = 0; nt < 16; nt++) {
        const int col = n_base + nt * 8 + tig * 2;
        if (r0 < N_NODES) {
            *reinterpret_cast<__half2*>(g_h16 + (size_t)r0 * HCOLS + col) =
                __float22half2_rn(make_float2(acc[nt][0], acc[nt][1]));
        }
        if (r0 + 8 < N_NODES) {
            *reinterpret_cast<__half2*>(g_h16 + (size_t)(r0 + 8) * HCOLS + col) =
                __float22half2_rn(make_float2(acc[nt][2], acc[nt][3]));
        }
    }
}

// ---------------------------------------------------------------------------
// Kernel 2: per-edge gather (fp16 h) + weighted combine + vector atomics.
// Block: 256 threads = 32 edges (8 threads/edge, 8 cols/thread).
// Phase 1: 128 threads compute 32x4 Gaussian weights (1 exp/lane) into smem.
// Phase 2: each thread: 4x LDG.128 of h[src] (one per kernel k), combine,
//          2x red.global.add.v4.f32 into out[dst].
// Grid = 1.6M/32 = 50000 exact.
// ---------------------------------------------------------------------------
__global__ __launch_bounds__(256) void edge_kernel(
    const float* __restrict__ pseudo,     // [E,3]
    const int*   __restrict__ src,
    const int*   __restrict__ dst,
    const float* __restrict__ mu,         // [4,3]
    const float* __restrict__ inv_sigma,  // [4,3]
    float* __restrict__ out)
{
    __shared__ float4 sg[32];
    __shared__ int ssrc[32];
    __shared__ int sdst[32];

    const int tid = threadIdx.x;
    const int e0  = blockIdx.x * 32;

    if (tid < 128) {
        const int el = tid >> 2;
        const int k  = tid & 3;
        const int e  = e0 + el;
        float p0 = __ldg(pseudo + 3 * (size_t)e + 0);
        float p1 = __ldg(pseudo + 3 * (size_t)e + 1);
        float p2 = __ldg(pseudo + 3 * (size_t)e + 2);
        float m0 = __ldg(mu + 3 * k + 0);
        float m1 = __ldg(mu + 3 * k + 1);
        float m2 = __ldg(mu + 3 * k + 2);
        float s0 = __ldg(inv_sigma + 3 * k + 0);
        float s1 = __ldg(inv_sigma + 3 * k + 1);
        float s2 = __ldg(inv_sigma + 3 * k + 2);
        float dx = p0 - m0, dy = p1 - m1, dz = p2 - m2;
        float w = dx * dx * s0 * s0 + dy * dy * s1 * s1 + dz * dz * s2 * s2;
        reinterpret_cast<float*>(&sg[el])[k] = __expf(-0.5f * w);
        if (k == 0) {
            ssrc[el] = src[e];
            sdst[el] = dst[e];
        }
    }
    __syncthreads();

    const int el = tid >> 3;   // local edge 0..31
    const int c  = tid & 7;    // column octet: cols c*8 .. c*8+7
    const int s  = ssrc[el];
    const int d  = sdst[el];
    const float4 gw = sg[el];

    const uint4* hp = reinterpret_cast<const uint4*>(
        g_h16 + (size_t)s * HCOLS + c * 8);
    uint4 q0 = __ldg(hp + 0);    // k = 0 (64 halves = 8 uint4 per k)
    uint4 q1 = __ldg(hp + 8);    // k = 1
    uint4 q2 = __ldg(hp + 16);   // k = 2
    uint4 q3 = __ldg(hp + 24);   // k = 3

    float acc[8];
    #pragma unroll
    for (int j = 0; j < 8; j++) acc[j] = 0.f;

    const float gk[4] = {gw.x, gw.y, gw.z, gw.w};
    const uint4 qs[4] = {q0, q1, q2, q3};
    #pragma unroll
    for (int k = 0; k < 4; k++) {
        const uint32_t* w32 = &qs[k].x;
        #pragma unroll
        for (int j = 0; j < 4; j++) {
            float2 f = __half22float2(
                *reinterpret_cast<const __half2*>(&w32[j]));
            acc[2 * j + 0] += gk[k] * f.x;
            acc[2 * j + 1] += gk[k] * f.y;
        }
    }

    float* op = out + (size_t)d * OUT_F + c * 8;
    asm volatile(
        "red.global.add.v4.f32 [%0], {%1, %2, %3, %4};"
        :: "l"(op), "f"(acc[0]), "f"(acc[1]), "f"(acc[2]), "f"(acc[3])
        : "memory");
    asm volatile(
        "red.global.add.v4.f32 [%0], {%1, %2, %3, %4};"
        :: "l"(op + 4), "f"(acc[4]), "f"(acc[5]), "f"(acc[6]), "f"(acc[7])
        : "memory");
}

// ---------------------------------------------------------------------------
extern "C" void kernel_launch(void* const* d_in, const int* in_sizes, int n_in,
                              void* d_out, int out_size)
{
    const float* feat      = (const float*)d_in[0];
    const float* pseudo    = (const float*)d_in[1];
    const int*   src       = (const int*)d_in[2];
    const int*   dst       = (const int*)d_in[3];
    const float* W_fc      = (const float*)d_in[4];
    const float* mu        = (const float*)d_in[5];
    const float* inv_sigma = (const float*)d_in[6];
    const float* bias      = (const float*)d_in[7];
    float* out = (float*)d_out;

    proj_kernel<<<(N_NODES + 63) / 64, 256>>>(feat, W_fc, bias, out);
    edge_kernel<<<N_EDGES / 32, 256>>>(pseudo, src, dst, mu, inv_sigma, out);
}

// round 4
// speedup vs baseline: 2.3365x; 1.2013x over previous
#include <cuda_runtime.h>
#include <cuda_fp16.h>
#include <cstdint>
#include <cstddef>

#define N_NODES   100000
#define N_EDGES   1600000
#define IN_F      64
#define OUT_F     64
#define KK        4
#define CAP       64          // max edges binned per dst node (Poisson mean 16)
#define OVF_CAP   8192

// Static scratch (allowed; no allocations).
__device__ __half2 g_feat16[(size_t)N_NODES * 32];         // feat in fp16, [N][64]
__device__ int     g_deg[N_NODES];
__device__ uint4   g_rec[(size_t)N_NODES * CAP * 2];       // 32B records {g0..g3 | src}
__device__ __half2 g_agg[(size_t)N_NODES * 128];           // agg[N][256] fp16
__device__ int     g_ovf_cnt;
__device__ uint4   g_ovf[OVF_CAP * 2];

// ---------------------------------------------------------------------------
// k0: feat -> fp16, zero degree counters / overflow counter.
// ---------------------------------------------------------------------------
__global__ __launch_bounds__(256) void prep_kernel(const float* __restrict__ feat)
{
    const int gid    = blockIdx.x * 256 + threadIdx.x;
    const int stride = gridDim.x * 256;
    const int total  = N_NODES * 32;                // half2 count
    const float2* f2 = reinterpret_cast<const float2*>(feat);
    for (int i = gid; i < total; i += stride)
        g_feat16[i] = __float22half2_rn(f2[i]);
    if (gid < N_NODES) g_deg[gid] = 0;
    if (gid == 0)      g_ovf_cnt  = 0;
}

// ---------------------------------------------------------------------------
// k1: per-edge Gaussian weights + bin record into dst's slot list.
// 1 thread per edge. Grid = 1.6M/256 = 6250 exact.
// ---------------------------------------------------------------------------
__global__ __launch_bounds__(256) void bin_kernel(
    const float* __restrict__ pseudo,     // [E,3]
    const int*   __restrict__ src,
    const int*   __restrict__ dst,
    const float* __restrict__ mu,         // [4,3]
    const float* __restrict__ inv_sigma)  // [4,3]
{
    const int e = blockIdx.x * 256 + threadIdx.x;
    const float p0 = __ldg(pseudo + 3 * (size_t)e + 0);
    const float p1 = __ldg(pseudo + 3 * (size_t)e + 1);
    const float p2 = __ldg(pseudo + 3 * (size_t)e + 2);
    const int s = src[e];
    const int d = dst[e];

    float g[KK];
    #pragma unroll
    for (int k = 0; k < KK; k++) {
        float m0 = __ldg(mu + 3 * k + 0);
        float m1 = __ldg(mu + 3 * k + 1);
        float m2 = __ldg(mu + 3 * k + 2);
        float s0 = __ldg(inv_sigma + 3 * k + 0);
        float s1 = __ldg(inv_sigma + 3 * k + 1);
        float s2 = __ldg(inv_sigma + 3 * k + 2);
        float dx = p0 - m0, dy = p1 - m1, dz = p2 - m2;
        float w = dx * dx * s0 * s0 + dy * dy * s1 * s1 + dz * dz * s2 * s2;
        g[k] = __expf(-0.5f * w);
    }

    const int pos = atomicAdd(&g_deg[d], 1);
    if (pos < CAP) {
        const size_t sl = ((size_t)d * CAP + pos) * 2;
        g_rec[sl] = make_uint4(__float_as_uint(g[0]), __float_as_uint(g[1]),
                               __float_as_uint(g[2]), __float_as_uint(g[3]));
        g_rec[sl + 1] = make_uint4((unsigned)s, 0u, 0u, 0u);
    } else {
        const int oi = atomicAdd(&g_ovf_cnt, 1);
        if (oi < OVF_CAP) {
            g_ovf[oi * 2] = make_uint4(__float_as_uint(g[0]), __float_as_uint(g[1]),
                                       __float_as_uint(g[2]), __float_as_uint(g[3]));
            g_ovf[oi * 2 + 1] = make_uint4((unsigned)s, (unsigned)d, 0u, 0u);
        }
    }
}

// ---------------------------------------------------------------------------
// k2: aggregate. One warp per dst node; records staged to smem; per edge one
// warp-wide LDG.32 covers the full 128B feat16 row (1 wavefront/edge).
// Each lane accumulates its 2 columns for all 4 kernels in fp32. No atomics.
// Grid = 100000/8 = 12500 exact.
// ---------------------------------------------------------------------------
__global__ __launch_bounds__(256) void agg_kernel()
{
    __shared__ uint4 srec[8][CAP][2];   // 16 KB

    const int w    = threadIdx.x >> 5;
    const int lane = threadIdx.x & 31;
    const int v    = blockIdx.x * 8 + w;

    int d = g_deg[v];
    if (d > CAP) d = CAP;

    const size_t base = (size_t)v * CAP * 2;
    srec[w][lane][0]      = g_rec[base + lane * 2];
    srec[w][lane][1]      = g_rec[base + lane * 2 + 1];
    srec[w][lane + 32][0] = g_rec[base + (lane + 32) * 2];
    srec[w][lane + 32][1] = g_rec[base + (lane + 32) * 2 + 1];
    __syncwarp();

    float2 acc0 = make_float2(0.f, 0.f);
    float2 acc1 = make_float2(0.f, 0.f);
    float2 acc2 = make_float2(0.f, 0.f);
    float2 acc3 = make_float2(0.f, 0.f);

    #pragma unroll 2
    for (int i = 0; i < d; i++) {
        const float4 g = *reinterpret_cast<const float4*>(&srec[w][i][0]);
        const int s    = (int)srec[w][i][1].x;
        const float2 f = __half22float2(g_feat16[(size_t)s * 32 + lane]);
        acc0.x += g.x * f.x; acc0.y += g.x * f.y;
        acc1.x += g.y * f.x; acc1.y += g.y * f.y;
        acc2.x += g.z * f.x; acc2.y += g.z * f.y;
        acc3.x += g.w * f.x; acc3.y += g.w * f.y;
    }

    __half2* ar = g_agg + (size_t)v * 128;
    ar[0 * 32 + lane] = __float22half2_rn(acc0);
    ar[1 * 32 + lane] = __float22half2_rn(acc1);
    ar[2 * 32 + lane] = __float22half2_rn(acc2);
    ar[3 * 32 + lane] = __float22half2_rn(acc3);
}

// ---------------------------------------------------------------------------
// k3: out = agg @ W' + feat + bias   (HMMA, fp32 accum)
// A = agg [N,256] fp16. For k-chunk ch (ki = ch*64 + i), B[o][i] = W_fc[ch*64+o][i]
// (direct row copy, no transpose). Block: 256 thr, 64 rows x 64 cols, K=256.
// Warp tile m16 x n32: 4 n-tiles x 4 k-steps per chunk x 4 chunks.
// ---------------------------------------------------------------------------
__global__ __launch_bounds__(256) void gemm_kernel(
    const float* __restrict__ feat,
    const float* __restrict__ W,      // [256,64]
    const float* __restrict__ bias,
    float* __restrict__ out)
{
    __shared__ __half sA[64][72];
    __shared__ __half sB[64][72];

    const int tid  = threadIdx.x;
    const int row0 = blockIdx.x * 64;
    const int lane = tid & 31;
    const int wid  = tid >> 5;
    const int mb   = (wid & 3) * 16;
    const int nb   = (wid >> 2) * 32;
    const int g    = lane >> 2;
    const int tig  = lane & 3;

    float acc[4][4];
    #pragma unroll
    for (int nt = 0; nt < 4; nt++)
        acc[nt][0] = acc[nt][1] = acc[nt][2] = acc[nt][3] = 0.f;

    #pragma unroll
    for (int ch = 0; ch < 4; ch++) {
        __syncthreads();
        {   // stage A chunk: agg rows row0..row0+63, halves ch*64..ch*64+63
            const int r   = tid >> 2;
            const int sgm = tid & 3;
            int gr = row0 + r;
            if (gr >= N_NODES) gr = N_NODES - 1;
            const uint4* ap = reinterpret_cast<const uint4*>(
                g_agg + (size_t)gr * 128) + ch * 8 + sgm * 2;
            *reinterpret_cast<uint4*>(&sA[r][sgm * 16])     = ap[0];
            *reinterpret_cast<uint4*>(&sA[r][sgm * 16 + 8]) = ap[1];
        }
        {   // stage B: W rows ch*64+o (fp32 -> fp16)
            const int o   = tid >> 2;
            const int sgm = tid & 3;
            const float4* wp = reinterpret_cast<const float4*>(
                W + (size_t)(ch * 64 + o) * IN_F + sgm * 16);
            float4 v0 = __ldg(wp + 0), v1 = __ldg(wp + 1);
            float4 v2 = __ldg(wp + 2), v3 = __ldg(wp + 3);
            __half* bp = &sB[o][sgm * 16];
            *reinterpret_cast<__half2*>(bp + 0)  = __float22half2_rn(make_float2(v0.x, v0.y));
            *reinterpret_cast<__half2*>(bp + 2)  = __float22half2_rn(make_float2(v0.z, v0.w));
            *reinterpret_cast<__half2*>(bp + 4)  = __float22half2_rn(make_float2(v1.x, v1.y));
            *reinterpret_cast<__half2*>(bp + 6)  = __float22half2_rn(make_float2(v1.z, v1.w));
            *reinterpret_cast<__half2*>(bp + 8)  = __float22half2_rn(make_float2(v2.x, v2.y));
            *reinterpret_cast<__half2*>(bp + 10) = __float22half2_rn(make_float2(v2.z, v2.w));
            *reinterpret_cast<__half2*>(bp + 12) = __float22half2_rn(make_float2(v3.x, v3.y));
            *reinterpret_cast<__half2*>(bp + 14) = __float22half2_rn(make_float2(v3.z, v3.w));
        }
        __syncthreads();

        #pragma unroll
        for (int ks = 0; ks < 4; ks++) {
            const int k0 = ks * 16;
            uint32_t a0 = *reinterpret_cast<const uint32_t*>(&sA[mb + g    ][k0 + tig * 2    ]);
            uint32_t a1 = *reinterpret_cast<const uint32_t*>(&sA[mb + g + 8][k0 + tig * 2    ]);
            uint32_t a2 = *reinterpret_cast<const uint32_t*>(&sA[mb + g    ][k0 + tig * 2 + 8]);
            uint32_t a3 = *reinterpret_cast<const uint32_t*>(&sA[mb + g + 8][k0 + tig * 2 + 8]);
            #pragma unroll
            for (int nt = 0; nt < 4; nt++) {
                const int n = nb + nt * 8 + g;
                uint32_t b0 = *reinterpret_cast<const uint32_t*>(&sB[n][k0 + tig * 2    ]);
                uint32_t b1 = *reinterpret_cast<const uint32_t*>(&sB[n][k0 + tig * 2 + 8]);
                asm volatile(
                    "mma.sync.aligned.m16n8k16.row.col.f32.f16.f16.f32 "
                    "{%0,%1,%2,%3}, {%4,%5,%6,%7}, {%8,%9}, {%0,%1,%2,%3};"
                    : "+f"(acc[nt][0]), "+f"(acc[nt][1]),
                      "+f"(acc[nt][2]), "+f"(acc[nt][3])
                    : "r"(a0), "r"(a1), "r"(a2), "r"(a3), "r"(b0), "r"(b1));
            }
        }
    }

    // Epilogue: out = acc + feat + bias
    const int r0 = row0 + mb + g;
    const int r1 = r0 + 8;
    #pragma unroll
    for (int nt = 0; nt < 4; nt++) {
        const int col = nb + nt * 8 + tig * 2;
        const float2 b = *reinterpret_cast<const float2*>(bias + col);
        if (r0 < N_NODES) {
            const float2 f = *reinterpret_cast<const float2*>(
                feat + (size_t)r0 * IN_F + col);
            float2 o = make_float2(acc[nt][0] + f.x + b.x, acc[nt][1] + f.y + b.y);
            *reinterpret_cast<float2*>(out + (size_t)r0 * OUT_F + col) = o;
        }
        if (r1 < N_NODES) {
            const float2 f = *reinterpret_cast<const float2*>(
                feat + (size_t)r1 * IN_F + col);
            float2 o = make_float2(acc[nt][2] + f.x + b.x, acc[nt][3] + f.y + b.y);
            *reinterpret_cast<float2*>(out + (size_t)r1 * OUT_F + col) = o;
        }
    }
}

// ---------------------------------------------------------------------------
// k4: drain overflow edges (deg > CAP). Statistically never runs; exists for
// correctness. Exact fp32 path, atomics into the finished out.
// ---------------------------------------------------------------------------
__global__ void ovf_kernel(const float* __restrict__ feat,
                           const float* __restrict__ W,
                           float* __restrict__ out)
{
    int cnt = g_ovf_cnt;
    if (cnt > OVF_CAP) cnt = OVF_CAP;
    const int o = threadIdx.x & 63;
    for (int i = threadIdx.x >> 6; i < cnt; i += 4) {
        const float4 gg = *reinterpret_cast<const float4*>(&g_ovf[i * 2]);
        const int s = (int)g_ovf[i * 2 + 1].x;
        const int d = (int)g_ovf[i * 2 + 1].y;
        float val = 0.f;
        const float gk[4] = {gg.x, gg.y, gg.z, gg.w};
        for (int k = 0; k < KK; k++) {
            float hk = 0.f;
            for (int ii = 0; ii < IN_F; ii++)
                hk += W[(size_t)(k * 64 + o) * IN_F + ii] * feat[(size_t)s * IN_F + ii];
            val += gk[k] * hk;
        }
        atomicAdd(out + (size_t)d * OUT_F + o, val);
    }
}

// ---------------------------------------------------------------------------
extern "C" void kernel_launch(void* const* d_in, const int* in_sizes, int n_in,
                              void* d_out, int out_size)
{
    const float* feat      = (const float*)d_in[0];
    const float* pseudo    = (const float*)d_in[1];
    const int*   src       = (const int*)d_in[2];
    const int*   dst       = (const int*)d_in[3];
    const float* W_fc      = (const float*)d_in[4];
    const float* mu        = (const float*)d_in[5];
    const float* inv_sigma = (const float*)d_in[6];
    const float* bias      = (const float*)d_in[7];
    float* out = (float*)d_out;

    prep_kernel<<<3125, 256>>>(feat);
    bin_kernel<<<N_EDGES / 256, 256>>>(pseudo, src, dst, mu, inv_sigma);
    agg_kernel<<<N_NODES / 8, 256>>>();
    gemm_kernel<<<(N_NODES + 63) / 64, 256>>>(feat, W_fc, bias, out);
    ovf_kernel<<<1, 256>>>(feat, W_fc, out);
}